// round 1
// baseline (speedup 1.0000x reference)
#include <cuda_runtime.h>
#include <cuda_bf16.h>
#include <cstdint>

// SegmentSum: x[N_ROWS,128] f32, sorted index[N_ROWS] -> out[N_SEG,128] f32
// Strategy: one warp per 128-row chunk. Lane l owns float4 at column 4*l.
// Accumulate runs in registers; interior runs -> plain store, boundary runs
// (first/last of chunk, possibly shared with neighbor chunks) -> atomicAdd.

#define D_FEAT 128
#define ROWS_PER_WARP 128
#define WARPS_PER_BLOCK 8
#define THREADS_PER_BLOCK (WARPS_PER_BLOCK * 32)

__device__ __forceinline__ void flush_atomic(float* __restrict__ out, int seg,
                                             float4 a, int lane) {
    float* p = out + (size_t)seg * D_FEAT + lane * 4;
    atomicAdd(p + 0, a.x);
    atomicAdd(p + 1, a.y);
    atomicAdd(p + 2, a.z);
    atomicAdd(p + 3, a.w);
}

__device__ __forceinline__ void flush_store(float* __restrict__ out, int seg,
                                            float4 a, int lane) {
    reinterpret_cast<float4*>(out)[(size_t)seg * 32 + lane] = a;
}

__global__ void __launch_bounds__(THREADS_PER_BLOCK)
segment_sum_kernel(const float* __restrict__ x,
                   const int* __restrict__ index,
                   float* __restrict__ out,
                   int n_rows) {
    const int warp_global = (blockIdx.x * blockDim.x + threadIdx.x) >> 5;
    const int lane = threadIdx.x & 31;

    long start = (long)warp_global * ROWS_PER_WARP;
    if (start >= n_rows) return;
    long end = start + ROWS_PER_WARP;
    if (end > n_rows) end = n_rows;

    const float4* __restrict__ xv = reinterpret_cast<const float4*>(x);

    int cur = __ldg(&index[start]);
    float4 acc = make_float4(0.f, 0.f, 0.f, 0.f);
    bool first_run = true;  // first run may continue from previous chunk

    #pragma unroll 4
    for (long r = start; r < end; ++r) {
        // These two loads are independent of the flush branch -> compiler can
        // batch them across unrolled iterations for MLP.
        int idx = __ldg(&index[r]);
        float4 v = xv[r * 32 + lane];

        if (idx != cur) {
            if (first_run) {
                flush_atomic(out, cur, acc, lane);
                first_run = false;
            } else {
                flush_store(out, cur, acc, lane);  // interior run: exclusive
            }
            acc = make_float4(0.f, 0.f, 0.f, 0.f);
            cur = idx;
        }
        acc.x += v.x;
        acc.y += v.y;
        acc.z += v.z;
        acc.w += v.w;
    }
    // Last run may continue into the next chunk -> always atomic.
    flush_atomic(out, cur, acc, lane);
}

extern "C" void kernel_launch(void* const* d_in, const int* in_sizes, int n_in,
                              void* d_out, int out_size) {
    const float* x = (const float*)d_in[0];
    const int* index = (const int*)d_in[1];
    float* out = (float*)d_out;

    const int n_rows = in_sizes[1];  // index element count == row count

    // Output is poisoned; atomics and empty segments need zeros.
    cudaMemsetAsync(d_out, 0, (size_t)out_size * sizeof(float));

    const int n_warps = (n_rows + ROWS_PER_WARP - 1) / ROWS_PER_WARP;
    const int n_blocks = (n_warps + WARPS_PER_BLOCK - 1) / WARPS_PER_BLOCK;
    segment_sum_kernel<<<n_blocks, THREADS_PER_BLOCK>>>(x, index, out, n_rows);
}

// round 2
// speedup vs baseline: 1.3636x; 1.3636x over previous
#include <cuda_runtime.h>
#include <cuda_bf16.h>
#include <cstdint>

// SegmentSum: x[N_ROWS,128] f32, sorted index[N_ROWS] -> out[N_SEG,128] f32
//
// Ownership scheme (no atomics, no memset):
//  - Warp w covers rows [w*RPW, (w+1)*RPW). A segment is OWNED by the warp
//    whose chunk contains the segment's first row.
//  - Each warp skips the leading continuation run (owned by an earlier warp),
//    then scans forward accumulating in registers. It keeps scanning past its
//    chunk end until the segment containing its last owned row terminates.
//  - On every transition cur -> idx it detects, it stores acc (plain float4
//    store) and zeroes the empty-segment gap (cur+1 .. idx-1).
//  - Warp 0 zeroes segments before index[0]; the warp that reaches row
//    n_rows-1 zeroes segments after the last index.
// Every output row is written exactly once -> poisoned d_out is fine.

#define D_FEAT 128
#define ROWS_PER_WARP 64
#define WARPS_PER_BLOCK 8
#define THREADS_PER_BLOCK (WARPS_PER_BLOCK * 32)

__device__ __forceinline__ void store_seg(float* __restrict__ out, int seg,
                                          float4 a, int lane) {
    reinterpret_cast<float4*>(out)[(size_t)seg * 32 + lane] = a;
}

__device__ __forceinline__ void zero_range(float* __restrict__ out, int s0,
                                           int s1, int lane) {
    const float4 z = make_float4(0.f, 0.f, 0.f, 0.f);
    for (int s = s0; s < s1; ++s)
        reinterpret_cast<float4*>(out)[(size_t)s * 32 + lane] = z;
}

__global__ void __launch_bounds__(THREADS_PER_BLOCK)
segment_sum_kernel(const float* __restrict__ x,
                   const int* __restrict__ index,
                   float* __restrict__ out,
                   int n_rows, int n_seg) {
    const int warp_global = (blockIdx.x * blockDim.x + threadIdx.x) >> 5;
    const int lane = threadIdx.x & 31;

    long start = (long)warp_global * ROWS_PER_WARP;
    if (start >= n_rows) return;
    long end = start + ROWS_PER_WARP;
    if (end > n_rows) end = n_rows;

    const float4* __restrict__ xv = reinterpret_cast<const float4*>(x);

    long r = start;
    if (start > 0) {
        // Skip continuation of the previous chunk's last segment (not owned).
        const int prev = __ldg(&index[start - 1]);
        while (r < end && __ldg(&index[r]) == prev) ++r;
        if (r == end) return;  // entire chunk is a continuation
    } else {
        // Zero segments before the first index value.
        zero_range(out, 0, __ldg(&index[0]), lane);
    }

    int cur = __ldg(&index[r]);
    float4 acc = make_float4(0.f, 0.f, 0.f, 0.f);

    for (;;) {
        int idx = cur;
        // Accumulate the current run. Guard the data load on the index
        // compare so transition rows don't cost a wasted 512B row read.
        #pragma unroll 4
        for (; r < n_rows; ++r) {
            idx = __ldg(&index[r]);
            if (idx != cur) break;
            float4 v = xv[r * 32 + lane];
            acc.x += v.x;
            acc.y += v.y;
            acc.z += v.z;
            acc.w += v.w;
        }

        store_seg(out, cur, acc, lane);

        if (r >= n_rows) {
            // This warp owns the globally-last segment: zero the tail.
            zero_range(out, cur + 1, n_seg, lane);
            return;
        }

        // Zero empty segments between cur and idx (seen by exactly this warp).
        zero_range(out, cur + 1, idx, lane);

        if (r >= end) return;  // next segment starts in a later chunk

        cur = idx;
        acc = make_float4(0.f, 0.f, 0.f, 0.f);
    }
}

extern "C" void kernel_launch(void* const* d_in, const int* in_sizes, int n_in,
                              void* d_out, int out_size) {
    const float* x = (const float*)d_in[0];
    const int* index = (const int*)d_in[1];
    float* out = (float*)d_out;

    const int n_rows = in_sizes[1];
    const int n_seg = out_size / D_FEAT;

    const int n_warps = (n_rows + ROWS_PER_WARP - 1) / ROWS_PER_WARP;
    const int n_blocks = (n_warps + WARPS_PER_BLOCK - 1) / WARPS_PER_BLOCK;
    segment_sum_kernel<<<n_blocks, THREADS_PER_BLOCK>>>(x, index, out,
                                                        n_rows, n_seg);
}

// round 3
// speedup vs baseline: 1.5627x; 1.1460x over previous
#include <cuda_runtime.h>
#include <cuda_bf16.h>
#include <cstdint>

// SegmentSum: x[600000,128] f32, sorted index -> out[50000,128] f32
// Ownership scheme (R2) + decoupled batched loads (R3):
//  - Warp owns segments that START in its 64-row chunk.
//  - Main loop: batches of 8 rows; all index+row loads issued unconditionally
//    before run logic (register compares) -> MLP ~16 per warp.
//  - Chunk-entry skip and end-of-chunk spill use ballot-based warp-parallel
//    index scans so no serial dependent-load chains remain.
// Every output row written exactly once (poisoned d_out OK, no memset).

#define D_FEAT 128
#define ROWS_PER_WARP 64
#define U 8
#define THREADS_PER_BLOCK 128
#define FULL 0xffffffffu

__device__ __forceinline__ void store_seg(float* __restrict__ out, int seg,
                                          float4 a, int lane) {
    reinterpret_cast<float4*>(out)[(size_t)seg * 32 + lane] = a;
}

__device__ __forceinline__ void zero_range(float* __restrict__ out, int s0,
                                           int s1, int lane) {
    const float4 z = make_float4(0.f, 0.f, 0.f, 0.f);
    for (int s = s0; s < s1; ++s)
        reinterpret_cast<float4*>(out)[(size_t)s * 32 + lane] = z;
}

__global__ void __launch_bounds__(THREADS_PER_BLOCK, 8)
segment_sum_kernel(const float* __restrict__ x,
                   const int* __restrict__ index,
                   float* __restrict__ out,
                   int n_rows, int n_seg) {
    const int warp_global = (blockIdx.x * blockDim.x + threadIdx.x) >> 5;
    const int lane = threadIdx.x & 31;

    long start = (long)warp_global * ROWS_PER_WARP;
    if (start >= n_rows) return;
    long end = start + ROWS_PER_WARP;
    if (end > n_rows) end = n_rows;

    const float4* __restrict__ xv = reinterpret_cast<const float4*>(x);

    long r = start;
    if (start > 0) {
        // Warp-parallel skip of the continuation run (owned by earlier warp).
        const int prev = __ldg(&index[start - 1]);
        for (;;) {
            long rr = r + lane;
            int iv = (rr < n_rows) ? __ldg(&index[rr]) : prev + 1;
            unsigned diff = __ballot_sync(FULL, iv != prev);
            if (diff) { r += __ffs(diff) - 1; break; }
            r += 32;
            if (r >= end) return;  // whole chunk is a continuation
        }
        if (r >= end) return;
    } else {
        zero_range(out, 0, __ldg(&index[0]), lane);
    }

    int cur = __ldg(&index[r]);
    float4 acc = make_float4(0.f, 0.f, 0.f, 0.f);

    // ---- Main loop over owned rows in [r, end): batches of U ----
    while (r < end) {
        int nb = (int)(end - r);
        if (nb > U) nb = U;
        int id[U];
        float4 v[U];
        // Issue ALL loads first (independent of run logic) -> high MLP.
        #pragma unroll
        for (int i = 0; i < U; ++i) {
            if (i < nb) {
                id[i] = __ldg(&index[r + i]);
                v[i] = xv[(r + i) * 32 + lane];
            }
        }
        // Register-only run logic.
        #pragma unroll
        for (int i = 0; i < U; ++i) {
            if (i < nb) {
                if (id[i] != cur) {
                    store_seg(out, cur, acc, lane);
                    zero_range(out, cur + 1, id[i], lane);
                    cur = id[i];
                    acc = make_float4(0.f, 0.f, 0.f, 0.f);
                }
                acc.x += v[i].x;
                acc.y += v[i].y;
                acc.z += v[i].z;
                acc.w += v[i].w;
            }
        }
        r += nb;
    }

    // ---- Spill: current run (owned) may continue past chunk end ----
    for (;;) {
        if (r >= n_rows) {  // globally last segment: store + zero tail
            store_seg(out, cur, acc, lane);
            zero_range(out, cur + 1, n_seg, lane);
            return;
        }
        long rr = r + lane;
        int iv = (rr < n_rows) ? __ldg(&index[rr]) : cur + 1;
        unsigned diff = __ballot_sync(FULL, iv != cur);
        int k = diff ? (__ffs(diff) - 1) : 32;  // rows r..r+k-1 belong to cur
        // Accumulate k rows; addresses independent -> batched loads.
        #pragma unroll 4
        for (int i = 0; i < k; ++i) {
            float4 t = xv[(r + i) * 32 + lane];
            acc.x += t.x;
            acc.y += t.y;
            acc.z += t.z;
            acc.w += t.w;
        }
        r += k;
        if (r >= n_rows) {
            store_seg(out, cur, acc, lane);
            zero_range(out, cur + 1, n_seg, lane);
            return;
        }
        if (k < 32) {  // transition at row r, next segment owned by later warp
            int nxt = __shfl_sync(FULL, iv, k);
            store_seg(out, cur, acc, lane);
            zero_range(out, cur + 1, nxt, lane);
            return;
        }
    }
}

extern "C" void kernel_launch(void* const* d_in, const int* in_sizes, int n_in,
                              void* d_out, int out_size) {
    const float* x = (const float*)d_in[0];
    const int* index = (const int*)d_in[1];
    float* out = (float*)d_out;

    const int n_rows = in_sizes[1];
    const int n_seg = out_size / D_FEAT;

    const int n_warps = (n_rows + ROWS_PER_WARP - 1) / ROWS_PER_WARP;
    const int warps_per_block = THREADS_PER_BLOCK / 32;
    const int n_blocks = (n_warps + warps_per_block - 1) / warps_per_block;
    segment_sum_kernel<<<n_blocks, THREADS_PER_BLOCK>>>(x, index, out,
                                                        n_rows, n_seg);
}